// round 1
// baseline (speedup 1.0000x reference)
#include <cuda_runtime.h>
#include <cuda_bf16.h>

// Problem constants
#define NB   8      // batch
#define NH   8      // heads
#define ND   32     // dim per head
#define NN   1024   // tokens (32*32)
#define CDIM 256    // channel dim
#define QKV_M 768   // 3*DIM_HEAD
__device__ __constant__ float kScale = 0.17677669529663687f; // 32^-0.5

// Scratch (device globals — no allocation allowed)
__device__ float g_qt[NB * NH * NN * ND]; // scaled Q, [b][h][n][d]
__device__ float g_kt[NB * NH * NN * ND]; // K, [b][h][n][d]
__device__ float g_vt[NB * NH * NN * ND]; // V, [b][h][n][d]
__device__ float g_ao[NB * CDIM * NN];    // attention out, [b][c][n]

// ---------------------------------------------------------------------------
// Tiled fp32 GEMM: C(MxN) = A(MxK) * B(KxN), tile 64x64, K-step 16,
// 256 threads, 4x4 micro-tile per thread.
// ---------------------------------------------------------------------------
#define TM 64
#define TN 64
#define TK 16
#define APAD 4

// Kernel 1: QKV projection + scatter to head-major scratch.
__global__ __launch_bounds__(256) void qkv_gemm_kernel(
    const float* __restrict__ W,   // [768, 256]
    const float* __restrict__ X)   // [B, 256, 1024]
{
    __shared__ float As[TK][TM + APAD];
    __shared__ float Bs[TK][TN];

    const int b  = blockIdx.z;
    const int m0 = blockIdx.y * TM;
    const int n0 = blockIdx.x * TN;
    const float* Bmat = X + (size_t)b * CDIM * NN;

    const int tid = threadIdx.x;
    const int tx = tid & 15;        // n direction
    const int ty = tid >> 4;        // m direction

    float acc[4][4];
    #pragma unroll
    for (int i = 0; i < 4; i++)
        #pragma unroll
        for (int j = 0; j < 4; j++) acc[i][j] = 0.f;

    for (int k0 = 0; k0 < CDIM; k0 += TK) {
        // Load A tile 64x16 (transpose into As[k][m])
        {
            int row = tid >> 2;           // 0..63
            int col = (tid & 3) * 4;      // 0,4,8,12
            float4 a = *(const float4*)&W[(m0 + row) * CDIM + k0 + col];
            As[col + 0][row] = a.x;
            As[col + 1][row] = a.y;
            As[col + 2][row] = a.z;
            As[col + 3][row] = a.w;
        }
        // Load B tile 16x64
        {
            int row = tid >> 4;           // 0..15
            int col = (tid & 15) * 4;
            *(float4*)&Bs[row][col] = *(const float4*)&Bmat[(k0 + row) * NN + n0 + col];
        }
        __syncthreads();
        #pragma unroll
        for (int k = 0; k < TK; k++) {
            float a[4], bb[4];
            *(float4*)a  = *(const float4*)&As[k][ty * 4];
            *(float4*)bb = *(const float4*)&Bs[k][tx * 4];
            #pragma unroll
            for (int i = 0; i < 4; i++)
                #pragma unroll
                for (int j = 0; j < 4; j++) acc[i][j] += a[i] * bb[j];
        }
        __syncthreads();
    }

    // Scatter: o<256 -> Q (scaled), o<512 -> K, else V, layout [b][h][n][d]
    #pragma unroll
    for (int i = 0; i < 4; i++) {
        int o   = m0 + ty * 4 + i;
        int grp = o >> 8;
        int hh  = (o >> 5) & 7;
        int dd  = o & 31;
        float* dst = (grp == 0) ? g_qt : (grp == 1) ? g_kt : g_vt;
        float sc = (grp == 0) ? kScale : 1.0f;
        size_t base = ((size_t)(b * NH + hh) * NN) * ND + dd;
        #pragma unroll
        for (int j = 0; j < 4; j++) {
            int n = n0 + tx * 4 + j;
            dst[base + (size_t)n * ND] = acc[i][j] * sc;
        }
    }
}

// ---------------------------------------------------------------------------
// Kernel 2: attention, one thread per query, online softmax, K/V streamed
// through smem in 64-row tiles.
// ---------------------------------------------------------------------------
#define JT 64

__global__ __launch_bounds__(256) void attn_kernel()
{
    const int b = blockIdx.z;
    const int h = blockIdx.y;
    const int i = blockIdx.x * 256 + threadIdx.x;

    const size_t headBase = (size_t)(b * NH + h) * NN * ND;
    const float* qrow = &g_qt[headBase + (size_t)i * ND];

    float q[ND];
    #pragma unroll
    for (int u = 0; u < 8; u++) ((float4*)q)[u] = ((const float4*)qrow)[u];

    float m = -1e30f, l = 0.f;
    float o[ND];
    #pragma unroll
    for (int u = 0; u < ND; u++) o[u] = 0.f;

    __shared__ float4 Ks[JT * 8];
    __shared__ float4 Vs[JT * 8];
    const float4* Kg = (const float4*)&g_kt[headBase];
    const float4* Vg = (const float4*)&g_vt[headBase];

    for (int j0 = 0; j0 < NN; j0 += JT) {
        __syncthreads();
        // 512 float4 each; 256 threads load 2 apiece
        Ks[threadIdx.x]       = Kg[j0 * 8 + threadIdx.x];
        Ks[threadIdx.x + 256] = Kg[j0 * 8 + threadIdx.x + 256];
        Vs[threadIdx.x]       = Vg[j0 * 8 + threadIdx.x];
        Vs[threadIdx.x + 256] = Vg[j0 * 8 + threadIdx.x + 256];
        __syncthreads();

        for (int jj = 0; jj < JT; jj++) {
            // s = q . k_j  (4 parallel accumulator chains)
            float s0 = 0.f, s1 = 0.f, s2 = 0.f, s3 = 0.f;
            #pragma unroll
            for (int u = 0; u < 8; u++) {
                float4 kk = Ks[jj * 8 + u];
                s0 += q[4 * u + 0] * kk.x;
                s1 += q[4 * u + 1] * kk.y;
                s2 += q[4 * u + 2] * kk.z;
                s3 += q[4 * u + 3] * kk.w;
            }
            float s = (s0 + s1) + (s2 + s3);

            if (s > m) {
                float corr = __expf(m - s);
                m = s;
                l *= corr;
                #pragma unroll
                for (int u = 0; u < ND; u++) o[u] *= corr;
            }
            float p = __expf(s - m);
            l += p;
            #pragma unroll
            for (int u = 0; u < 8; u++) {
                float4 vv = Vs[jj * 8 + u];
                o[4 * u + 0] += p * vv.x;
                o[4 * u + 1] += p * vv.y;
                o[4 * u + 2] += p * vv.z;
                o[4 * u + 3] += p * vv.w;
            }
        }
    }

    const float inv = 1.0f / l;
    // write [b][c][n] with c = h*32+d; consecutive threads -> consecutive n (coalesced)
    float* ao = &g_ao[((size_t)b * CDIM + h * ND) * NN + i];
    #pragma unroll
    for (int u = 0; u < ND; u++) ao[(size_t)u * NN] = o[u] * inv;
}

// ---------------------------------------------------------------------------
// Kernel 3: output projection + bias: Y[b][o][n] = W_out @ AO + b_out
// ---------------------------------------------------------------------------
__global__ __launch_bounds__(256) void out_gemm_kernel(
    const float* __restrict__ W,     // [256, 256]
    const float* __restrict__ bias,  // [256]
    float* __restrict__ Y)           // [B, 256, 1024]
{
    __shared__ float As[TK][TM + APAD];
    __shared__ float Bs[TK][TN];

    const int b  = blockIdx.z;
    const int m0 = blockIdx.y * TM;
    const int n0 = blockIdx.x * TN;
    const float* Bmat = g_ao + (size_t)b * CDIM * NN;

    const int tid = threadIdx.x;
    const int tx = tid & 15;
    const int ty = tid >> 4;

    float acc[4][4];
    #pragma unroll
    for (int i = 0; i < 4; i++)
        #pragma unroll
        for (int j = 0; j < 4; j++) acc[i][j] = 0.f;

    for (int k0 = 0; k0 < CDIM; k0 += TK) {
        {
            int row = tid >> 2;
            int col = (tid & 3) * 4;
            float4 a = *(const float4*)&W[(m0 + row) * CDIM + k0 + col];
            As[col + 0][row] = a.x;
            As[col + 1][row] = a.y;
            As[col + 2][row] = a.z;
            As[col + 3][row] = a.w;
        }
        {
            int row = tid >> 4;
            int col = (tid & 15) * 4;
            *(float4*)&Bs[row][col] = *(const float4*)&Bmat[(k0 + row) * NN + n0 + col];
        }
        __syncthreads();
        #pragma unroll
        for (int k = 0; k < TK; k++) {
            float a[4], bb[4];
            *(float4*)a  = *(const float4*)&As[k][ty * 4];
            *(float4*)bb = *(const float4*)&Bs[k][tx * 4];
            #pragma unroll
            for (int i = 0; i < 4; i++)
                #pragma unroll
                for (int j = 0; j < 4; j++) acc[i][j] += a[i] * bb[j];
        }
        __syncthreads();
    }

    #pragma unroll
    for (int i = 0; i < 4; i++) {
        int o = m0 + ty * 4 + i;
        float bv = bias[o];
        float* yrow = Y + ((size_t)b * CDIM + o) * NN + n0 + tx * 4;
        #pragma unroll
        for (int j = 0; j < 4; j++) yrow[j] = acc[i][j] + bv;
    }
}

// ---------------------------------------------------------------------------
extern "C" void kernel_launch(void* const* d_in, const int* in_sizes, int n_in,
                              void* d_out, int out_size)
{
    const float* x     = (const float*)d_in[0];
    const float* w_qkv = (const float*)d_in[1];
    const float* w_out = (const float*)d_in[2];
    const float* b_out = (const float*)d_in[3];
    float* y = (float*)d_out;

    qkv_gemm_kernel<<<dim3(NN / TN, QKV_M / TM, NB), 256>>>(w_qkv, x);
    attn_kernel<<<dim3(NN / 256, NH, NB), 256>>>();
    out_gemm_kernel<<<dim3(NN / TN, CDIM / TM, NB), 256>>>(w_out, b_out, y);
}

// round 2
// speedup vs baseline: 3.4104x; 3.4104x over previous
#include <cuda_runtime.h>
#include <cuda_bf16.h>
#include <cstdint>

// Problem constants
#define NB   8      // batch
#define NH   8      // heads
#define ND   32     // dim per head
#define NN   1024   // tokens (32*32)
#define CDIM 256    // channel dim
#define QKV_M 768   // 3*DIM_HEAD
#define SCALE_F 0.17677669529663687f
#define L2E 1.4426950408889634f

// Scratch (device globals — no allocation allowed)
__device__ float g_qt[NB * NH * NN * ND]; // scaled Q, [b][h][n][d]
__device__ float g_kt[NB * NH * NN * ND]; // K, [b][h][n][d]
__device__ float g_vt[NB * NH * NN * ND]; // V, [b][h][n][d]
__device__ float g_ao[NB * CDIM * NN];    // attention out, [b][c][n]

// ---------------------------------------------------------------------------
// tf32 helpers
// ---------------------------------------------------------------------------
__device__ __forceinline__ uint32_t f2tf(float x) {
    uint32_t r;
    asm("cvt.rna.tf32.f32 %0, %1;" : "=r"(r) : "f"(x));
    return r;
}

__device__ __forceinline__ void mma_tf32(float c[4],
                                         uint32_t a0, uint32_t a1, uint32_t a2, uint32_t a3,
                                         uint32_t b0, uint32_t b1) {
    asm volatile(
        "mma.sync.aligned.m16n8k8.row.col.f32.tf32.tf32.f32 "
        "{%0,%1,%2,%3}, {%4,%5,%6,%7}, {%8,%9}, {%0,%1,%2,%3};\n"
        : "+f"(c[0]), "+f"(c[1]), "+f"(c[2]), "+f"(c[3])
        : "r"(a0), "r"(a1), "r"(a2), "r"(a3), "r"(b0), "r"(b1));
}

__device__ __forceinline__ float ex2f(float x) {
    float r;
    asm("ex2.approx.ftz.f32 %0, %1;" : "=f"(r) : "f"(x));
    return r;
}

// ---------------------------------------------------------------------------
// tf32 MMA GEMM: C(MxN) = A(MxK)*B(KxN), K=256, N=1024, tile 128x128x32.
// 256 threads = 8 warps as 4(m) x 2(n); warp tile 32x64.
// A pad 36: frag bank = (4g+tig) unique. B pad 136: (8tig+g) unique.
// ---------------------------------------------------------------------------
#define GBM 128
#define GBN 128
#define GBK 32
#define APAD 36
#define BPAD 136

struct GemmAcc {
    float acc[2][8][4];
};

__device__ __forceinline__ void gemm_core(const float* __restrict__ Ag, // [M,256] row at m0
                                          const float* __restrict__ Bg, // [256,1024] at n0
                                          int m0, int n0, GemmAcc& R)
{
    __shared__ uint32_t As[GBM][APAD];
    __shared__ uint32_t Bs[GBK][BPAD];

    const int tid = threadIdx.x;
    const int warp = tid >> 5;
    const int lane = tid & 31;
    const int g = lane >> 2;      // groupID
    const int tig = lane & 3;     // thread in group
    const int wm = (warp >> 1) * 32;   // warp m offset
    const int wn = (warp & 1) * 64;    // warp n offset

    #pragma unroll
    for (int mt = 0; mt < 2; mt++)
        #pragma unroll
        for (int nt = 0; nt < 8; nt++)
            #pragma unroll
            for (int r = 0; r < 4; r++) R.acc[mt][nt][r] = 0.f;

    for (int k0 = 0; k0 < CDIM; k0 += GBK) {
        // Load A tile 128x32 (1024 float4 slots)
        #pragma unroll
        for (int i = 0; i < 4; i++) {
            int slot = i * 256 + tid;
            int row = slot >> 3;
            int f4 = slot & 7;
            float4 a = *(const float4*)&Ag[(m0 + row) * CDIM + k0 + 4 * f4];
            uint4 u;
            u.x = f2tf(a.x); u.y = f2tf(a.y); u.z = f2tf(a.z); u.w = f2tf(a.w);
            *(uint4*)&As[row][4 * f4] = u;
        }
        // Load B tile 32x128
        #pragma unroll
        for (int i = 0; i < 4; i++) {
            int slot = i * 256 + tid;
            int row = slot >> 5;
            int f4 = slot & 31;
            float4 b = *(const float4*)&Bg[(k0 + row) * NN + n0 + 4 * f4];
            uint4 u;
            u.x = f2tf(b.x); u.y = f2tf(b.y); u.z = f2tf(b.z); u.w = f2tf(b.w);
            *(uint4*)&Bs[row][4 * f4] = u;
        }
        __syncthreads();

        #pragma unroll
        for (int ks = 0; ks < 4; ks++) {
            int kk = ks * 8;
            // A frags for 2 m-tiles
            uint32_t af[2][4];
            #pragma unroll
            for (int mt = 0; mt < 2; mt++) {
                int r = wm + 16 * mt;
                af[mt][0] = As[r + g][kk + tig];
                af[mt][1] = As[r + g + 8][kk + tig];
                af[mt][2] = As[r + g][kk + tig + 4];
                af[mt][3] = As[r + g + 8][kk + tig + 4];
            }
            #pragma unroll
            for (int nt = 0; nt < 8; nt++) {
                uint32_t b0 = Bs[kk + tig][wn + 8 * nt + g];
                uint32_t b1 = Bs[kk + tig + 4][wn + 8 * nt + g];
                mma_tf32(R.acc[0][nt], af[0][0], af[0][1], af[0][2], af[0][3], b0, b1);
                mma_tf32(R.acc[1][nt], af[1][0], af[1][1], af[1][2], af[1][3], b0, b1);
            }
        }
        __syncthreads();
    }
}

// Kernel 1: QKV projection, scatter to head-major scratch.
__global__ __launch_bounds__(256) void qkv_gemm_kernel(
    const float* __restrict__ W,   // [768, 256]
    const float* __restrict__ X)   // [B, 256, 1024]
{
    const int b = blockIdx.z;
    const int m0 = blockIdx.y * GBM;
    const int n0 = blockIdx.x * GBN;

    GemmAcc R;
    gemm_core(W, X + (size_t)b * CDIM * NN, m0, n0, R);

    const int tid = threadIdx.x;
    const int warp = tid >> 5;
    const int lane = tid & 31;
    const int g = lane >> 2;
    const int tig = lane & 3;
    const int wm = (warp >> 1) * 32;
    const int wn = (warp & 1) * 64;

    #pragma unroll
    for (int mt = 0; mt < 2; mt++) {
        #pragma unroll
        for (int half = 0; half < 2; half++) {
            int o = m0 + wm + 16 * mt + g + 8 * half;
            int grp = o >> 8;
            int hh = (o >> 5) & 7;
            int dd = o & 31;
            float* dst = (grp == 0) ? g_qt : (grp == 1) ? g_kt : g_vt;
            float sc = (grp == 0) ? SCALE_F : 1.0f;
            size_t base = ((size_t)(b * NH + hh) * NN) * ND + dd;
            #pragma unroll
            for (int nt = 0; nt < 8; nt++) {
                int n = n0 + wn + 8 * nt + 2 * tig;
                dst[base + (size_t)n * ND]       = R.acc[mt][nt][2 * half]     * sc;
                dst[base + (size_t)(n + 1) * ND] = R.acc[mt][nt][2 * half + 1] * sc;
            }
        }
    }
}

// Kernel 3: output projection + bias.
__global__ __launch_bounds__(256) void out_gemm_kernel(
    const float* __restrict__ W,     // [256, 256]
    const float* __restrict__ bias,  // [256]
    float* __restrict__ Y)           // [B, 256, 1024]
{
    const int b = blockIdx.z;
    const int m0 = blockIdx.y * GBM;
    const int n0 = blockIdx.x * GBN;

    GemmAcc R;
    gemm_core(W, g_ao + (size_t)b * CDIM * NN, m0, n0, R);

    const int tid = threadIdx.x;
    const int warp = tid >> 5;
    const int lane = tid & 31;
    const int g = lane >> 2;
    const int tig = lane & 3;
    const int wm = (warp >> 1) * 32;
    const int wn = (warp & 1) * 64;

    #pragma unroll
    for (int mt = 0; mt < 2; mt++) {
        #pragma unroll
        for (int half = 0; half < 2; half++) {
            int o = m0 + wm + 16 * mt + g + 8 * half;
            float bv = bias[o];
            float* yrow = Y + ((size_t)b * CDIM + o) * NN;
            #pragma unroll
            for (int nt = 0; nt < 8; nt++) {
                int n = n0 + wn + 8 * nt + 2 * tig;
                yrow[n]     = R.acc[mt][nt][2 * half]     + bv;
                yrow[n + 1] = R.acc[mt][nt][2 * half + 1] + bv;
            }
        }
    }
}

// ---------------------------------------------------------------------------
// Kernel 2: flash attention, tf32 MMA. CTA = 128 threads (4 warps),
// Br=64 queries (16/warp), Bc=64 keys per tile, d=32.
// ---------------------------------------------------------------------------
#define KPAD 36   // (4g+tig) unique
#define VPAD 40   // (8tig+g) unique
#define PPAD 68   // (4g+tig) unique

__global__ __launch_bounds__(128) void attn_kernel()
{
    __shared__ uint32_t Qs[64][KPAD];
    __shared__ uint32_t Ks[64][KPAD];
    __shared__ uint32_t Vs[64][VPAD];
    __shared__ uint32_t Ps[4][16][PPAD];

    const int b = blockIdx.z;
    const int h = blockIdx.y;
    const int q0 = blockIdx.x * 64;

    const int tid = threadIdx.x;
    const int warp = tid >> 5;
    const int lane = tid & 31;
    const int g = lane >> 2;
    const int tig = lane & 3;

    const size_t headBase = (size_t)(b * NH + h) * NN * ND;
    const float* Qg = g_qt + headBase;
    const float* Kg = g_kt + headBase;
    const float* Vg = g_vt + headBase;

    // Load Q tile (64x32) -> Qs (tf32)
    #pragma unroll
    for (int i = 0; i < 4; i++) {
        int slot = i * 128 + tid;
        int row = slot >> 3;
        int f4 = slot & 7;
        float4 qv = *(const float4*)&Qg[(size_t)(q0 + row) * ND + 4 * f4];
        uint4 u;
        u.x = f2tf(qv.x); u.y = f2tf(qv.y); u.z = f2tf(qv.z); u.w = f2tf(qv.w);
        *(uint4*)&Qs[row][4 * f4] = u;
    }
    __syncthreads();

    // Hoist Q frags: warp owns rows [16*warp, 16*warp+16)
    uint32_t qf[4][4];
    #pragma unroll
    for (int ks = 0; ks < 4; ks++) {
        int kk = 8 * ks;
        int r = 16 * warp;
        qf[ks][0] = Qs[r + g][kk + tig];
        qf[ks][1] = Qs[r + g + 8][kk + tig];
        qf[ks][2] = Qs[r + g][kk + tig + 4];
        qf[ks][3] = Qs[r + g + 8][kk + tig + 4];
    }

    float oacc[4][4];  // O [16 x 32]: 4 d-tiles
    #pragma unroll
    for (int dt = 0; dt < 4; dt++)
        #pragma unroll
        for (int r = 0; r < 4; r++) oacc[dt][r] = 0.f;
    float m0 = -1e30f, m1 = -1e30f, l0 = 0.f, l1 = 0.f;

    for (int t = 0; t < NN / 64; t++) {
        int j0 = t * 64;
        __syncthreads();  // prior PV done reading Vs / S done reading Ks
        // Load K, V tiles (64x32 each)
        #pragma unroll
        for (int i = 0; i < 4; i++) {
            int slot = i * 128 + tid;
            int row = slot >> 3;
            int f4 = slot & 7;
            float4 kv = *(const float4*)&Kg[(size_t)(j0 + row) * ND + 4 * f4];
            uint4 u;
            u.x = f2tf(kv.x); u.y = f2tf(kv.y); u.z = f2tf(kv.z); u.w = f2tf(kv.w);
            *(uint4*)&Ks[row][4 * f4] = u;
            float4 vv = *(const float4*)&Vg[(size_t)(j0 + row) * ND + 4 * f4];
            uint4 w;
            w.x = f2tf(vv.x); w.y = f2tf(vv.y); w.z = f2tf(vv.z); w.w = f2tf(vv.w);
            *(uint4*)&Vs[row][4 * f4] = w;
        }
        __syncthreads();

        // S = Q K^T : [16 x 64] per warp
        float sacc[8][4];
        #pragma unroll
        for (int nt = 0; nt < 8; nt++)
            #pragma unroll
            for (int r = 0; r < 4; r++) sacc[nt][r] = 0.f;
        #pragma unroll
        for (int ks = 0; ks < 4; ks++) {
            int kk = 8 * ks;
            #pragma unroll
            for (int nt = 0; nt < 8; nt++) {
                uint32_t b0 = Ks[8 * nt + g][kk + tig];
                uint32_t b1 = Ks[8 * nt + g][kk + tig + 4];
                mma_tf32(sacc[nt], qf[ks][0], qf[ks][1], qf[ks][2], qf[ks][3], b0, b1);
            }
        }

        // Online softmax. Thread holds rows {g, g+8}, cols {8nt+2tig, +1}
        float mx0 = -1e30f, mx1 = -1e30f;
        #pragma unroll
        for (int nt = 0; nt < 8; nt++) {
            mx0 = fmaxf(mx0, fmaxf(sacc[nt][0], sacc[nt][1]));
            mx1 = fmaxf(mx1, fmaxf(sacc[nt][2], sacc[nt][3]));
        }
        mx0 = fmaxf(mx0, __shfl_xor_sync(0xffffffff, mx0, 1));
        mx0 = fmaxf(mx0, __shfl_xor_sync(0xffffffff, mx0, 2));
        mx1 = fmaxf(mx1, __shfl_xor_sync(0xffffffff, mx1, 1));
        mx1 = fmaxf(mx1, __shfl_xor_sync(0xffffffff, mx1, 2));

        float mn0 = fmaxf(m0, mx0);
        float mn1 = fmaxf(m1, mx1);
        float sc0 = ex2f((m0 - mn0) * L2E);
        float sc1 = ex2f((m1 - mn1) * L2E);
        m0 = mn0; m1 = mn1;
        float mb0 = mn0 * L2E, mb1 = mn1 * L2E;

        float sum0 = 0.f, sum1 = 0.f;
        float p[8][4];
        #pragma unroll
        for (int nt = 0; nt < 8; nt++) {
            p[nt][0] = ex2f(fmaf(sacc[nt][0], L2E, -mb0));
            p[nt][1] = ex2f(fmaf(sacc[nt][1], L2E, -mb0));
            p[nt][2] = ex2f(fmaf(sacc[nt][2], L2E, -mb1));
            p[nt][3] = ex2f(fmaf(sacc[nt][3], L2E, -mb1));
            sum0 += p[nt][0] + p[nt][1];
            sum1 += p[nt][2] + p[nt][3];
        }
        sum0 += __shfl_xor_sync(0xffffffff, sum0, 1);
        sum0 += __shfl_xor_sync(0xffffffff, sum0, 2);
        sum1 += __shfl_xor_sync(0xffffffff, sum1, 1);
        sum1 += __shfl_xor_sync(0xffffffff, sum1, 2);
        l0 = l0 * sc0 + sum0;
        l1 = l1 * sc1 + sum1;

        // Rescale O
        #pragma unroll
        for (int dt = 0; dt < 4; dt++) {
            oacc[dt][0] *= sc0; oacc[dt][1] *= sc0;
            oacc[dt][2] *= sc1; oacc[dt][3] *= sc1;
        }

        // Store P (tf32) to warp-private buffer
        #pragma unroll
        for (int nt = 0; nt < 8; nt++) {
            uint2 u0, u1;
            u0.x = f2tf(p[nt][0]); u0.y = f2tf(p[nt][1]);
            u1.x = f2tf(p[nt][2]); u1.y = f2tf(p[nt][3]);
            *(uint2*)&Ps[warp][g][8 * nt + 2 * tig]     = u0;
            *(uint2*)&Ps[warp][g + 8][8 * nt + 2 * tig] = u1;
        }
        __syncwarp();

        // O += P V : A = P [16x64], B = V [64x32]
        #pragma unroll
        for (int ks2 = 0; ks2 < 8; ks2++) {
            int kk = 8 * ks2;
            uint32_t a0 = Ps[warp][g][kk + tig];
            uint32_t a1 = Ps[warp][g + 8][kk + tig];
            uint32_t a2 = Ps[warp][g][kk + tig + 4];
            uint32_t a3 = Ps[warp][g + 8][kk + tig + 4];
            #pragma unroll
            for (int dt = 0; dt < 4; dt++) {
                uint32_t b0 = Vs[kk + tig][8 * dt + g];
                uint32_t b1 = Vs[kk + tig + 4][8 * dt + g];
                mma_tf32(oacc[dt], a0, a1, a2, a3, b0, b1);
            }
        }
        __syncwarp();
    }

    // Epilogue: normalize, write [b][c][n] with c = h*32+d, n = q0+16w+row
    float inv0 = 1.0f / l0;
    float inv1 = 1.0f / l1;
    int n_row0 = q0 + 16 * warp + g;
    float* aoB = g_ao + ((size_t)b * CDIM + h * ND) * NN;
    #pragma unroll
    for (int dt = 0; dt < 4; dt++) {
        int d = 8 * dt + 2 * tig;
        aoB[(size_t)d * NN + n_row0]           = oacc[dt][0] * inv0;
        aoB[(size_t)(d + 1) * NN + n_row0]     = oacc[dt][1] * inv0;
        aoB[(size_t)d * NN + n_row0 + 8]       = oacc[dt][2] * inv1;
        aoB[(size_t)(d + 1) * NN + n_row0 + 8] = oacc[dt][3] * inv1;
    }
}

// ---------------------------------------------------------------------------
extern "C" void kernel_launch(void* const* d_in, const int* in_sizes, int n_in,
                              void* d_out, int out_size)
{
    const float* x     = (const float*)d_in[0];
    const float* w_qkv = (const float*)d_in[1];
    const float* w_out = (const float*)d_in[2];
    const float* b_out = (const float*)d_in[3];
    float* y = (float*)d_out;

    qkv_gemm_kernel<<<dim3(NN / GBN, QKV_M / GBM, NB), 256>>>(w_qkv, x);
    attn_kernel<<<dim3(NN / 64, NH, NB), 128>>>();
    out_gemm_kernel<<<dim3(NN / GBN, CDIM / GBM, NB), 256>>>(w_out, b_out, y);
}